// round 1
// baseline (speedup 1.0000x reference)
#include <cuda_runtime.h>
#include <math.h>

#define D_MODEL 2048
#define NH 32
#define NKV 8
#define DK 64
#define BATCH 2
#define SEQ 1024
#define ROWS (BATCH*SEQ)   // 2048

// Scratch (static device memory; no allocations allowed)
__device__ float g_q[ROWS * D_MODEL];          // [b*S+s][h*64+d]
__device__ float g_k[ROWS * NKV * DK];         // [b*S+s][kvh*64+d]
__device__ float g_v[ROWS * NKV * DK];
__device__ float g_att[ROWS * D_MODEL];

// ---------------------------------------------------------------------------
// SGEMM: C[M,N] = A[M,K] @ B[K,N] + bias[N].  BM=BN=128, BK=8, 8x8 per thread.
// Assumes M%128==0, N%128==0, K%8==0 (true for all calls here).
// ---------------------------------------------------------------------------
__global__ __launch_bounds__(256) void sgemm_bias(
        const float* __restrict__ A, const float* __restrict__ B,
        const float* __restrict__ bias, float* __restrict__ C,
        int M, int N, int K) {
    const int BM = 128, BN = 128, BK = 8;
    __shared__ float As[BK][BM];
    __shared__ float Bs[BK][BN];

    int tx = threadIdx.x;
    int brow = blockIdx.y * BM;
    int bcol = blockIdx.x * BN;

    int aRow = tx >> 1;            // 0..127
    int aCol = (tx & 1) << 2;      // 0 or 4
    int bRow = tx >> 5;            // 0..7
    int bCol = (tx & 31) << 2;     // 0..124

    int trow = (tx >> 4) << 3;     // 0..120 step 8
    int tcol = (tx & 15) << 3;     // 0..120 step 8

    float acc[8][8];
    #pragma unroll
    for (int i = 0; i < 8; i++)
        #pragma unroll
        for (int j = 0; j < 8; j++) acc[i][j] = 0.f;

    for (int k0 = 0; k0 < K; k0 += BK) {
        float4 a4 = *(const float4*)(A + (size_t)(brow + aRow) * K + k0 + aCol);
        As[aCol + 0][aRow] = a4.x;
        As[aCol + 1][aRow] = a4.y;
        As[aCol + 2][aRow] = a4.z;
        As[aCol + 3][aRow] = a4.w;
        float4 b4 = *(const float4*)(B + (size_t)(k0 + bRow) * N + bcol + bCol);
        *(float4*)(&Bs[bRow][bCol]) = b4;
        __syncthreads();

        #pragma unroll
        for (int kk = 0; kk < BK; kk++) {
            float ar[8], br[8];
            #pragma unroll
            for (int i = 0; i < 8; i += 4) {
                float4 t = *(const float4*)(&As[kk][trow + i]);
                ar[i] = t.x; ar[i+1] = t.y; ar[i+2] = t.z; ar[i+3] = t.w;
            }
            #pragma unroll
            for (int j = 0; j < 8; j += 4) {
                float4 t = *(const float4*)(&Bs[kk][tcol + j]);
                br[j] = t.x; br[j+1] = t.y; br[j+2] = t.z; br[j+3] = t.w;
            }
            #pragma unroll
            for (int i = 0; i < 8; i++)
                #pragma unroll
                for (int j = 0; j < 8; j++)
                    acc[i][j] += ar[i] * br[j];
        }
        __syncthreads();
    }

    #pragma unroll
    for (int i = 0; i < 8; i++) {
        float* crow = C + (size_t)(brow + trow + i) * N + bcol + tcol;
        #pragma unroll
        for (int j = 0; j < 8; j += 4) {
            float4 r;
            r.x = acc[i][j + 0] + bias[bcol + tcol + j + 0];
            r.y = acc[i][j + 1] + bias[bcol + tcol + j + 1];
            r.z = acc[i][j + 2] + bias[bcol + tcol + j + 2];
            r.w = acc[i][j + 3] + bias[bcol + tcol + j + 3];
            *(float4*)(crow + j) = r;
        }
    }
}

// ---------------------------------------------------------------------------
// RoPE in-place on tensor of shape [ROWS][nheads*DK] (interleaved pairs).
// ---------------------------------------------------------------------------
__global__ void rope_kernel(float* __restrict__ t, int nheads, int total) {
    int i = blockIdx.x * blockDim.x + threadIdx.x;
    if (i >= total) return;
    int p   = i & 31;                       // 0..31  (DK/2 = 32)
    int h   = (i >> 5) % nheads;
    int row = i / (nheads * 32);
    int pos = row & (SEQ - 1);

    float inv = powf(10000.0f, -(float)p / 32.0f);
    float ang = (float)pos * inv;
    float sn, cs;
    sincosf(ang, &sn, &cs);

    float* ptr = t + ((size_t)row * nheads + h) * DK + 2 * p;
    float e = ptr[0], o = ptr[1];
    ptr[0] = e * cs - o * sn;
    ptr[1] = e * sn + o * cs;
}

// ---------------------------------------------------------------------------
// Causal GQA flash attention. 64 queries/block, 1 thread per query.
// q row + accumulator in registers; K/V tiles in shared (broadcast reads).
// Writes output in [b][s][h*64+d] layout (ready for output projection).
// ---------------------------------------------------------------------------
__global__ __launch_bounds__(64) void attn_kernel(
        const float* __restrict__ q, const float* __restrict__ k,
        const float* __restrict__ v, float* __restrict__ o) {
    __shared__ float ks[32][DK];
    __shared__ float vs[32][DK];
    __shared__ float ps[64][33];   // raw scores, padded

    int tid = threadIdx.x;           // 0..63 = query within tile
    int bh  = blockIdx.y;
    int b   = bh >> 5;
    int h   = bh & 31;
    int kvh = h >> 2;                // N_REP = 4
    int q0  = blockIdx.x << 6;

    // load q row, pre-scaled by 1/sqrt(DK)
    float rq[DK];
    const float* qrow = q + ((size_t)(b * SEQ + q0 + tid) * NH + h) * DK;
    #pragma unroll
    for (int d = 0; d < DK; d += 4) {
        float4 t = *(const float4*)(qrow + d);
        rq[d] = t.x * 0.125f; rq[d+1] = t.y * 0.125f;
        rq[d+2] = t.z * 0.125f; rq[d+3] = t.w * 0.125f;
    }

    float m = -1e30f, l = 0.f;
    float acc[DK];
    #pragma unroll
    for (int d = 0; d < DK; d++) acc[d] = 0.f;

    int kend = q0 + 64;
    for (int kt = 0; kt < kend; kt += 32) {
        // cooperative load of 32x64 K and V tiles (512 float4s, 64 threads)
        #pragma unroll
        for (int it = 0; it < 8; it++) {
            int f4i = it * 64 + tid;        // 0..511
            int r  = f4i >> 4;              // 0..31
            int c  = (f4i & 15) << 2;       // 0..60
            size_t src = ((size_t)(b * SEQ + kt + r) * NKV + kvh) * DK + c;
            *(float4*)(&ks[r][c]) = *(const float4*)(k + src);
            *(float4*)(&vs[r][c]) = *(const float4*)(v + src);
        }
        __syncthreads();

        float tmax = -1e30f;
        int lim = q0 + tid - kt;            // keys j<=lim are causal-valid
        for (int j = 0; j < 32; j++) {
            float s0 = 0.f, s1 = 0.f, s2 = 0.f, s3 = 0.f;
            #pragma unroll
            for (int d = 0; d < DK; d += 4) {
                s0 += rq[d    ] * ks[j][d    ];
                s1 += rq[d + 1] * ks[j][d + 1];
                s2 += rq[d + 2] * ks[j][d + 2];
                s3 += rq[d + 3] * ks[j][d + 3];
            }
            float s = (s0 + s1) + (s2 + s3);
            if (j > lim) s = -1e30f;
            tmax = fmaxf(tmax, s);
            ps[tid][j] = s;
        }

        float mnew = fmaxf(m, tmax);
        float corr = __expf(m - mnew);
        m = mnew;
        l *= corr;
        #pragma unroll
        for (int d = 0; d < DK; d++) acc[d] *= corr;

        for (int j = 0; j < 32; j++) {
            float p = __expf(ps[tid][j] - mnew);
            l += p;
            #pragma unroll
            for (int d = 0; d < DK; d++)
                acc[d] += p * vs[j][d];
        }
        __syncthreads();
    }

    float invl = 1.f / l;
    float* orow = o + (size_t)(b * SEQ + q0 + tid) * D_MODEL + h * DK;
    #pragma unroll
    for (int d = 0; d < DK; d += 4) {
        float4 t;
        t.x = acc[d] * invl; t.y = acc[d+1] * invl;
        t.z = acc[d+2] * invl; t.w = acc[d+3] * invl;
        *(float4*)(orow + d) = t;
    }
}

// ---------------------------------------------------------------------------
extern "C" void kernel_launch(void* const* d_in, const int* in_sizes, int n_in,
                              void* d_out, int out_size) {
    const float* x  = (const float*)d_in[0];
    const float* Wq = (const float*)d_in[1];
    const float* bq = (const float*)d_in[2];
    const float* Wk = (const float*)d_in[3];
    const float* bk = (const float*)d_in[4];
    const float* Wv = (const float*)d_in[5];
    const float* bv = (const float*)d_in[6];
    const float* Wo = (const float*)d_in[7];
    const float* bo = (const float*)d_in[8];
    float* out = (float*)d_out;

    float *q, *k, *v, *att;
    cudaGetSymbolAddress((void**)&q,   g_q);
    cudaGetSymbolAddress((void**)&k,   g_k);
    cudaGetSymbolAddress((void**)&v,   g_v);
    cudaGetSymbolAddress((void**)&att, g_att);

    // QKV projections
    sgemm_bias<<<dim3(D_MODEL/128, ROWS/128), 256>>>(x, Wq, bq, q, ROWS, D_MODEL, D_MODEL);
    sgemm_bias<<<dim3((NKV*DK)/128, ROWS/128), 256>>>(x, Wk, bk, k, ROWS, NKV*DK, D_MODEL);
    sgemm_bias<<<dim3((NKV*DK)/128, ROWS/128), 256>>>(x, Wv, bv, v, ROWS, NKV*DK, D_MODEL);

    // RoPE on q and k
    {
        int totq = ROWS * NH * (DK/2);
        rope_kernel<<<(totq + 255)/256, 256>>>(q, NH, totq);
        int totk = ROWS * NKV * (DK/2);
        rope_kernel<<<(totk + 255)/256, 256>>>(k, NKV, totk);
    }

    // Attention
    attn_kernel<<<dim3(SEQ/64, BATCH*NH), 64>>>(q, k, v, att);

    // Output projection
    sgemm_bias<<<dim3(D_MODEL/128, ROWS/128), 256>>>(att, Wo, bo, out, ROWS, D_MODEL, D_MODEL);
}

// round 4
// speedup vs baseline: 3.1219x; 3.1219x over previous
#include <cuda_runtime.h>
#include <cstdint>
#include <math.h>

#define D_MODEL 2048
#define NH 32
#define NKV 8
#define DK 64
#define BATCH 2
#define SEQ 1024
#define ROWS (BATCH*SEQ)   // 2048

// Scratch (static device memory; no allocations allowed)
__device__ float g_q[ROWS * D_MODEL];
__device__ float g_k[ROWS * NKV * DK];
__device__ float g_v[ROWS * NKV * DK];
__device__ float g_att[ROWS * D_MODEL];

__device__ __forceinline__ float to_tf32(float x) {
    float r;
    asm("cvt.rna.tf32.f32 %0, %1;" : "=f"(r) : "f"(x));
    return r;
}

// m16n8k8 tf32 mma: D = A@B + D (fp32 accumulate)
__device__ __forceinline__ void mma8(float* c, const uint32_t* a, const uint32_t* b) {
    asm volatile(
        "mma.sync.aligned.m16n8k8.row.col.f32.tf32.tf32.f32 "
        "{%0,%1,%2,%3}, {%4,%5,%6,%7}, {%8,%9}, {%0,%1,%2,%3};"
        : "+f"(c[0]), "+f"(c[1]), "+f"(c[2]), "+f"(c[3])
        : "r"(a[0]), "r"(a[1]), "r"(a[2]), "r"(a[3]),
          "r"(b[0]), "r"(b[1]));
}

// ---------------------------------------------------------------------------
// tf32 tensor-core GEMM: C[M,N] = A[M,K] @ B[K,N] + bias[N]
// CTA tile 128x128, BK=32. 256 threads = 8 warps (2x4), warp tile 64x32.
// Requires M%128==0, N%128==0, K%32==0.
// ---------------------------------------------------------------------------
#define SA_STRIDE 36    // 128 rows x (32 k + pad 4)
#define SB_STRIDE 136   // 32 k-rows x (128 n + pad 8)

__global__ __launch_bounds__(256) void gemm_tf32mma(
        const float* __restrict__ A, const float* __restrict__ B,
        const float* __restrict__ bias, float* __restrict__ C,
        int M, int N, int K) {
    __shared__ float sA[128 * SA_STRIDE];
    __shared__ float sB[32 * SB_STRIDE];

    const int tid  = threadIdx.x;
    const int lane = tid & 31;
    const int wid  = tid >> 5;
    const int wm   = wid >> 2;          // 0..1
    const int wn   = wid & 3;           // 0..3
    const int g    = lane >> 2;         // group id 0..7
    const int t    = lane & 3;          // thread in group 0..3
    const int brow = blockIdx.y * 128;
    const int bcol = blockIdx.x * 128;

    float acc[4][4][4] = {};

    const int arow = tid >> 3;          // base row for A loads (with +32*it? no: i pattern)
    const int ac4  = tid & 7;
    const int bkr  = tid >> 5;          // 0..7
    const int bn4  = tid & 31;

    for (int k0 = 0; k0 < K; k0 += 32) {
        // A tile: 128x32 floats = 1024 float4, 4 iters x 256 threads
        #pragma unroll
        for (int it = 0; it < 4; it++) {
            int r = arow + it * 32;
            float4 v = *(const float4*)(A + (size_t)(brow + r) * K + k0 + ac4 * 4);
            v.x = to_tf32(v.x); v.y = to_tf32(v.y);
            v.z = to_tf32(v.z); v.w = to_tf32(v.w);
            *(float4*)(sA + r * SA_STRIDE + ac4 * 4) = v;
        }
        // B tile: 32x128 floats, coalesced rows of W
        #pragma unroll
        for (int it = 0; it < 4; it++) {
            int kk = bkr + it * 8;
            float4 v = *(const float4*)(B + (size_t)(k0 + kk) * N + bcol + bn4 * 4);
            v.x = to_tf32(v.x); v.y = to_tf32(v.y);
            v.z = to_tf32(v.z); v.w = to_tf32(v.w);
            *(float4*)(sB + kk * SB_STRIDE + bn4 * 4) = v;
        }
        __syncthreads();

        #pragma unroll
        for (int ks = 0; ks < 4; ks++) {
            const int kb = ks * 8;
            uint32_t af[4][4];
            #pragma unroll
            for (int mi = 0; mi < 4; mi++) {
                const float* base = sA + (wm * 64 + mi * 16) * SA_STRIDE + kb;
                af[mi][0] = __float_as_uint(base[g * SA_STRIDE + t]);
                af[mi][1] = __float_as_uint(base[(g + 8) * SA_STRIDE + t]);
                af[mi][2] = __float_as_uint(base[g * SA_STRIDE + t + 4]);
                af[mi][3] = __float_as_uint(base[(g + 8) * SA_STRIDE + t + 4]);
            }
            uint32_t bf[4][2];
            #pragma unroll
            for (int ni = 0; ni < 4; ni++) {
                const float* base = sB + kb * SB_STRIDE + wn * 32 + ni * 8;
                bf[ni][0] = __float_as_uint(base[t * SB_STRIDE + g]);
                bf[ni][1] = __float_as_uint(base[(t + 4) * SB_STRIDE + g]);
            }
            #pragma unroll
            for (int mi = 0; mi < 4; mi++)
                #pragma unroll
                for (int ni = 0; ni < 4; ni++)
                    mma8(acc[mi][ni], af[mi], bf[ni]);
        }
        __syncthreads();
    }

    // Epilogue: write fp32 + bias
    #pragma unroll
    for (int mi = 0; mi < 4; mi++) {
        int r0 = brow + wm * 64 + mi * 16 + g;
        #pragma unroll
        for (int ni = 0; ni < 4; ni++) {
            int c0 = bcol + wn * 32 + ni * 8 + t * 2;
            float2 bv = *(const float2*)(bias + c0);
            float2 o0, o1;
            o0.x = acc[mi][ni][0] + bv.x;
            o0.y = acc[mi][ni][1] + bv.y;
            o1.x = acc[mi][ni][2] + bv.x;
            o1.y = acc[mi][ni][3] + bv.y;
            *(float2*)(C + (size_t)r0 * N + c0) = o0;
            *(float2*)(C + (size_t)(r0 + 8) * N + c0) = o1;
        }
    }
}

// ---------------------------------------------------------------------------
// RoPE in-place on tensor of shape [ROWS][nheads*DK] (interleaved pairs).
// ---------------------------------------------------------------------------
__global__ void rope_kernel(float* __restrict__ t, int nheads, int total) {
    int i = blockIdx.x * blockDim.x + threadIdx.x;
    if (i >= total) return;
    int p   = i & 31;
    int h   = (i >> 5) % nheads;
    int row = i / (nheads * 32);
    int pos = row & (SEQ - 1);

    float inv = powf(10000.0f, -(float)p / 32.0f);
    float ang = (float)pos * inv;
    float sn, cs;
    sincosf(ang, &sn, &cs);

    float* ptr = t + ((size_t)row * nheads + h) * DK + 2 * p;
    float e = ptr[0], o = ptr[1];
    ptr[0] = e * cs - o * sn;
    ptr[1] = e * sn + o * cs;
}

// ---------------------------------------------------------------------------
// Causal GQA flash attention (fp32). 64 queries/block, 1 thread per query.
// ---------------------------------------------------------------------------
__global__ __launch_bounds__(64) void attn_kernel(
        const float* __restrict__ q, const float* __restrict__ k,
        const float* __restrict__ v, float* __restrict__ o) {
    __shared__ float ks[32][DK];
    __shared__ float vs[32][DK];
    __shared__ float ps[64][33];

    int tid = threadIdx.x;
    int bh  = blockIdx.y;
    int b   = bh >> 5;
    int h   = bh & 31;
    int kvh = h >> 2;
    int q0  = blockIdx.x << 6;

    float rq[DK];
    const float* qrow = q + ((size_t)(b * SEQ + q0 + tid) * NH + h) * DK;
    #pragma unroll
    for (int d = 0; d < DK; d += 4) {
        float4 t = *(const float4*)(qrow + d);
        rq[d] = t.x * 0.125f; rq[d+1] = t.y * 0.125f;
        rq[d+2] = t.z * 0.125f; rq[d+3] = t.w * 0.125f;
    }

    float m = -1e30f, l = 0.f;
    float acc[DK];
    #pragma unroll
    for (int d = 0; d < DK; d++) acc[d] = 0.f;

    int kend = q0 + 64;
    for (int kt = 0; kt < kend; kt += 32) {
        #pragma unroll
        for (int it = 0; it < 8; it++) {
            int f4i = it * 64 + tid;
            int r  = f4i >> 4;
            int c  = (f4i & 15) << 2;
            size_t src = ((size_t)(b * SEQ + kt + r) * NKV + kvh) * DK + c;
            *(float4*)(&ks[r][c]) = *(const float4*)(k + src);
            *(float4*)(&vs[r][c]) = *(const float4*)(v + src);
        }
        __syncthreads();

        float tmax = -1e30f;
        int lim = q0 + tid - kt;
        for (int j = 0; j < 32; j++) {
            float s0 = 0.f, s1 = 0.f, s2 = 0.f, s3 = 0.f;
            #pragma unroll
            for (int d = 0; d < DK; d += 4) {
                s0 += rq[d    ] * ks[j][d    ];
                s1 += rq[d + 1] * ks[j][d + 1];
                s2 += rq[d + 2] * ks[j][d + 2];
                s3 += rq[d + 3] * ks[j][d + 3];
            }
            float s = (s0 + s1) + (s2 + s3);
            if (j > lim) s = -1e30f;
            tmax = fmaxf(tmax, s);
            ps[tid][j] = s;
        }

        float mnew = fmaxf(m, tmax);
        float corr = __expf(m - mnew);
        m = mnew;
        l *= corr;
        #pragma unroll
        for (int d = 0; d < DK; d++) acc[d] *= corr;

        for (int j = 0; j < 32; j++) {
            float p = __expf(ps[tid][j] - mnew);
            l += p;
            #pragma unroll
            for (int d = 0; d < DK; d++)
                acc[d] += p * vs[j][d];
        }
        __syncthreads();
    }

    float invl = 1.f / l;
    float* orow = o + (size_t)(b * SEQ + q0 + tid) * D_MODEL + h * DK;
    #pragma unroll
    for (int d = 0; d < DK; d += 4) {
        float4 t;
        t.x = acc[d] * invl; t.y = acc[d+1] * invl;
        t.z = acc[d+2] * invl; t.w = acc[d+3] * invl;
        *(float4*)(orow + d) = t;
    }
}

// ---------------------------------------------------------------------------
extern "C" void kernel_launch(void* const* d_in, const int* in_sizes, int n_in,
                              void* d_out, int out_size) {
    const float* x  = (const float*)d_in[0];
    const float* Wq = (const float*)d_in[1];
    const float* bq = (const float*)d_in[2];
    const float* Wk = (const float*)d_in[3];
    const float* bk = (const float*)d_in[4];
    const float* Wv = (const float*)d_in[5];
    const float* bv = (const float*)d_in[6];
    const float* Wo = (const float*)d_in[7];
    const float* bo = (const float*)d_in[8];
    float* out = (float*)d_out;

    float *q, *k, *v, *att;
    cudaGetSymbolAddress((void**)&q,   g_q);
    cudaGetSymbolAddress((void**)&k,   g_k);
    cudaGetSymbolAddress((void**)&v,   g_v);
    cudaGetSymbolAddress((void**)&att, g_att);

    // QKV projections (tf32 tensor cores)
    gemm_tf32mma<<<dim3(D_MODEL/128, ROWS/128), 256>>>(x, Wq, bq, q, ROWS, D_MODEL, D_MODEL);
    gemm_tf32mma<<<dim3((NKV*DK)/128, ROWS/128), 256>>>(x, Wk, bk, k, ROWS, NKV*DK, D_MODEL);
    gemm_tf32mma<<<dim3((NKV*DK)/128, ROWS/128), 256>>>(x, Wv, bv, v, ROWS, NKV*DK, D_MODEL);

    // RoPE on q and k
    {
        int totq = ROWS * NH * (DK/2);
        rope_kernel<<<(totq + 255)/256, 256>>>(q, NH, totq);
        int totk = ROWS * NKV * (DK/2);
        rope_kernel<<<(totk + 255)/256, 256>>>(k, NKV, totk);
    }

    // Attention
    attn_kernel<<<dim3(SEQ/64, BATCH*NH), 64>>>(q, k, v, att);

    // Output projection
    gemm_tf32mma<<<dim3(D_MODEL/128, ROWS/128), 256>>>(att, Wo, bo, out, ROWS, D_MODEL, D_MODEL);
}

// round 7
// speedup vs baseline: 6.3084x; 2.0207x over previous
#include <cuda_runtime.h>
#include <cstdint>
#include <math.h>

#define D_MODEL 2048
#define NH 32
#define NKV 8
#define DK 64
#define BATCH 2
#define SEQ 1024
#define ROWS (BATCH*SEQ)   // 2048

__device__ float g_q[ROWS * D_MODEL];
__device__ float g_k[ROWS * NKV * DK];
__device__ float g_v[ROWS * NKV * DK];
__device__ float g_att[ROWS * D_MODEL];

__device__ __forceinline__ float to_tf32(float x) {
    float r;
    asm("cvt.rna.tf32.f32 %0, %1;" : "=f"(r) : "f"(x));
    return r;
}
__device__ __forceinline__ uint32_t to_tf32_u(float x) {
    float r;
    asm("cvt.rna.tf32.f32 %0, %1;" : "=f"(r) : "f"(x));
    return __float_as_uint(r);
}

// m16n8k8 tf32 mma: D = A@B + D (fp32 accumulate)
__device__ __forceinline__ void mma8(float* c, const uint32_t* a, const uint32_t* b) {
    asm volatile(
        "mma.sync.aligned.m16n8k8.row.col.f32.tf32.tf32.f32 "
        "{%0,%1,%2,%3}, {%4,%5,%6,%7}, {%8,%9}, {%0,%1,%2,%3};"
        : "+f"(c[0]), "+f"(c[1]), "+f"(c[2]), "+f"(c[3])
        : "r"(a[0]), "r"(a[1]), "r"(a[2]), "r"(a[3]),
          "r"(b[0]), "r"(b[1]));
}

// ---------------------------------------------------------------------------
// tf32 tensor-core GEMM with register-prefetch double buffering.
// C[M,N] = A[M,K] @ B[K,N] + bias[N]. CTA 128x128, BK=32, 8 warps (2x4).
// ---------------------------------------------------------------------------
#define SA_STRIDE 36
#define SB_STRIDE 136

struct GemmSmem {
    float sA[128 * SA_STRIDE];
    float sB[32 * SB_STRIDE];
};

__device__ __forceinline__ void gemm_body(
        const float* __restrict__ A, const float* __restrict__ B,
        const float* __restrict__ bias, float* __restrict__ C,
        int M, int N, int K, GemmSmem& sm,
        int brow, int bcol) {
    float* sA = sm.sA;
    float* sB = sm.sB;

    const int tid  = threadIdx.x;
    const int lane = tid & 31;
    const int wid  = tid >> 5;
    const int wm   = wid >> 2;
    const int wn   = wid & 3;
    const int g    = lane >> 2;
    const int t    = lane & 3;

    float acc[4][4][4] = {};

    const int arow = tid >> 3;
    const int ac4  = tid & 7;
    const int bkr  = tid >> 5;
    const int bn4  = tid & 31;

    const int nchunks = K >> 5;

    float4 pa[4], pb[4];
    #pragma unroll
    for (int it = 0; it < 4; it++) {
        pa[it] = *(const float4*)(A + (size_t)(brow + arow + it * 32) * K + ac4 * 4);
        pb[it] = *(const float4*)(B + (size_t)(bkr + it * 8) * N + bcol + bn4 * 4);
    }

    for (int c = 0; c < nchunks; c++) {
        // store current chunk (tf32-rounded)
        #pragma unroll
        for (int it = 0; it < 4; it++) {
            float4 v = pa[it];
            v.x = to_tf32(v.x); v.y = to_tf32(v.y);
            v.z = to_tf32(v.z); v.w = to_tf32(v.w);
            *(float4*)(sA + (arow + it * 32) * SA_STRIDE + ac4 * 4) = v;
            float4 w = pb[it];
            w.x = to_tf32(w.x); w.y = to_tf32(w.y);
            w.z = to_tf32(w.z); w.w = to_tf32(w.w);
            *(float4*)(sB + (bkr + it * 8) * SB_STRIDE + bn4 * 4) = w;
        }
        __syncthreads();

        // prefetch next chunk (latency hidden by mma below)
        if (c + 1 < nchunks) {
            const int k0 = (c + 1) << 5;
            #pragma unroll
            for (int it = 0; it < 4; it++) {
                pa[it] = *(const float4*)(A + (size_t)(brow + arow + it * 32) * K + k0 + ac4 * 4);
                pb[it] = *(const float4*)(B + (size_t)(k0 + bkr + it * 8) * N + bcol + bn4 * 4);
            }
        }

        #pragma unroll
        for (int ks = 0; ks < 4; ks++) {
            const int kb = ks * 8;
            uint32_t af[4][4];
            #pragma unroll
            for (int mi = 0; mi < 4; mi++) {
                const float* base = sA + (wm * 64 + mi * 16) * SA_STRIDE + kb;
                af[mi][0] = __float_as_uint(base[g * SA_STRIDE + t]);
                af[mi][1] = __float_as_uint(base[(g + 8) * SA_STRIDE + t]);
                af[mi][2] = __float_as_uint(base[g * SA_STRIDE + t + 4]);
                af[mi][3] = __float_as_uint(base[(g + 8) * SA_STRIDE + t + 4]);
            }
            uint32_t bf[4][2];
            #pragma unroll
            for (int ni = 0; ni < 4; ni++) {
                const float* base = sB + kb * SB_STRIDE + wn * 32 + ni * 8;
                bf[ni][0] = __float_as_uint(base[t * SB_STRIDE + g]);
                bf[ni][1] = __float_as_uint(base[(t + 4) * SB_STRIDE + g]);
            }
            #pragma unroll
            for (int mi = 0; mi < 4; mi++)
                #pragma unroll
                for (int ni = 0; ni < 4; ni++)
                    mma8(acc[mi][ni], af[mi], bf[ni]);
        }
        __syncthreads();
    }

    #pragma unroll
    for (int mi = 0; mi < 4; mi++) {
        int r0 = brow + wm * 64 + mi * 16 + g;
        #pragma unroll
        for (int ni = 0; ni < 4; ni++) {
            int c0 = bcol + wn * 32 + ni * 8 + t * 2;
            float2 bv = *(const float2*)(bias + c0);
            float2 o0, o1;
            o0.x = acc[mi][ni][0] + bv.x;
            o0.y = acc[mi][ni][1] + bv.y;
            o1.x = acc[mi][ni][2] + bv.x;
            o1.y = acc[mi][ni][3] + bv.y;
            *(float2*)(C + (size_t)r0 * N + c0) = o0;
            *(float2*)(C + (size_t)(r0 + 8) * N + c0) = o1;
        }
    }
}

__global__ __launch_bounds__(256) void gemm_tf32mma(
        const float* __restrict__ A, const float* __restrict__ B,
        const float* __restrict__ bias, float* __restrict__ C,
        int M, int N, int K) {
    __shared__ GemmSmem sm;
    gemm_body(A, B, bias, C, M, N, K, sm,
              blockIdx.y * 128, blockIdx.x * 128);
}

// Fused K+V projection: blockIdx.z selects which weight/bias/output.
__global__ __launch_bounds__(256) void gemm_tf32mma_kv(
        const float* __restrict__ A,
        const float* __restrict__ Wk, const float* __restrict__ bk, float* __restrict__ Ck,
        const float* __restrict__ Wv, const float* __restrict__ bv, float* __restrict__ Cv,
        int M, int N, int K) {
    __shared__ GemmSmem sm;
    const float* B = (blockIdx.z == 0) ? Wk : Wv;
    const float* bias = (blockIdx.z == 0) ? bk : bv;
    float* C = (blockIdx.z == 0) ? Ck : Cv;
    gemm_body(A, B, bias, C, M, N, K, sm,
              blockIdx.y * 128, blockIdx.x * 128);
}

// ---------------------------------------------------------------------------
// RoPE in-place on tensor of shape [ROWS][nheads*DK] (interleaved pairs).
// ---------------------------------------------------------------------------
__global__ void rope_kernel(float* __restrict__ t, int nheads, int total) {
    int i = blockIdx.x * blockDim.x + threadIdx.x;
    if (i >= total) return;
    int p   = i & 31;
    int h   = (i >> 5) % nheads;
    int row = i / (nheads * 32);
    int pos = row & (SEQ - 1);

    float inv = powf(10000.0f, -(float)p / 32.0f);
    float ang = (float)pos * inv;
    float sn, cs;
    sincosf(ang, &sn, &cs);

    float* ptr = t + ((size_t)row * nheads + h) * DK + 2 * p;
    float e = ptr[0], o = ptr[1];
    ptr[0] = e * cs - o * sn;
    ptr[1] = e * sn + o * cs;
}

// ---------------------------------------------------------------------------
// tf32 mma flash attention. 64-query tile, 128 threads (4 warps, 16 rows each).
// Q fragments register-resident; K smem buffer reused for P; fp32 softmax.
// ---------------------------------------------------------------------------
#define AT_STRIDE 68

__global__ __launch_bounds__(128) void attn_mma(
        const float* __restrict__ q, const float* __restrict__ k,
        const float* __restrict__ v, float* __restrict__ o) {
    __shared__ float sKP[64 * AT_STRIDE];   // K tile, then reused for P
    __shared__ float sV[64 * AT_STRIDE];

    const int tid  = threadIdx.x;
    const int lane = tid & 31;
    const int w    = tid >> 5;       // 0..3 (warp -> 16 query rows)
    const int g    = lane >> 2;      // 0..7
    const int t    = lane & 3;       // 0..3

    const int bh  = blockIdx.y;
    const int b   = bh >> 5;
    const int h   = bh & 31;
    const int kvh = h >> 2;
    const int q0  = blockIdx.x << 6;

    // Q fragments, pre-scaled by 1/sqrt(DK) = 0.125
    uint32_t qf[8][4];
    {
        const float* qbase = q + ((size_t)(b * SEQ + q0 + w * 16) * NH + h) * DK;
        const size_t rs = (size_t)NH * DK;
        #pragma unroll
        for (int ks = 0; ks < 8; ks++) {
            int d0 = ks * 8 + t;
            qf[ks][0] = to_tf32_u(qbase[(size_t)g       * rs + d0    ] * 0.125f);
            qf[ks][1] = to_tf32_u(qbase[(size_t)(g + 8) * rs + d0    ] * 0.125f);
            qf[ks][2] = to_tf32_u(qbase[(size_t)g       * rs + d0 + 4] * 0.125f);
            qf[ks][3] = to_tf32_u(qbase[(size_t)(g + 8) * rs + d0 + 4] * 0.125f);
        }
    }

    float oacc[8][4] = {};
    float m0 = -1e30f, m1 = -1e30f, l0 = 0.f, l1 = 0.f;

    for (int kt = 0; kt <= q0; kt += 64) {
        // load K and V tiles (64 keys x 64 dims), tf32-rounded
        #pragma unroll
        for (int it = 0; it < 8; it++) {
            int idx = it * 128 + tid;
            int r  = idx >> 4;
            int c4 = (idx & 15) << 2;
            size_t src = ((size_t)(b * SEQ + kt + r) * NKV + kvh) * DK + c4;
            float4 kv4 = *(const float4*)(k + src);
            kv4.x = to_tf32(kv4.x); kv4.y = to_tf32(kv4.y);
            kv4.z = to_tf32(kv4.z); kv4.w = to_tf32(kv4.w);
            *(float4*)(sKP + r * AT_STRIDE + c4) = kv4;
            float4 vv4 = *(const float4*)(v + src);
            vv4.x = to_tf32(vv4.x); vv4.y = to_tf32(vv4.y);
            vv4.z = to_tf32(vv4.z); vv4.w = to_tf32(vv4.w);
            *(float4*)(sV + r * AT_STRIDE + c4) = vv4;
        }
        __syncthreads();

        // S = Q @ K^T  (16 x 64 per warp)
        float sc[8][4] = {};
        #pragma unroll
        for (int ks = 0; ks < 8; ks++) {
            const int kb = ks * 8;
            #pragma unroll
            for (int ni = 0; ni < 8; ni++) {
                uint32_t bf[2];
                const float* base = sKP + (ni * 8 + g) * AT_STRIDE + kb + t;
                bf[0] = __float_as_uint(base[0]);
                bf[1] = __float_as_uint(base[4]);
                mma8(sc[ni], qf[ks], bf);
            }
        }
        __syncthreads();   // all warps done reading K before P overwrite

        // causal mask on diagonal tile
        if (kt == q0) {
            int lr0 = w * 16 + g;
            int lr1 = lr0 + 8;
            #pragma unroll
            for (int ni = 0; ni < 8; ni++) {
                int lc = ni * 8 + 2 * t;
                if (lc     > lr0) sc[ni][0] = -1e30f;
                if (lc + 1 > lr0) sc[ni][1] = -1e30f;
                if (lc     > lr1) sc[ni][2] = -1e30f;
                if (lc + 1 > lr1) sc[ni][3] = -1e30f;
            }
        }

        // row max (across ni regs, then across the 4 t-lanes)
        float tm0 = -1e30f, tm1 = -1e30f;
        #pragma unroll
        for (int ni = 0; ni < 8; ni++) {
            tm0 = fmaxf(tm0, fmaxf(sc[ni][0], sc[ni][1]));
            tm1 = fmaxf(tm1, fmaxf(sc[ni][2], sc[ni][3]));
        }
        tm0 = fmaxf(tm0, __shfl_xor_sync(0xffffffffu, tm0, 1));
        tm0 = fmaxf(tm0, __shfl_xor_sync(0xffffffffu, tm0, 2));
        tm1 = fmaxf(tm1, __shfl_xor_sync(0xffffffffu, tm1, 1));
        tm1 = fmaxf(tm1, __shfl_xor_sync(0xffffffffu, tm1, 2));

        float mn0 = fmaxf(m0, tm0);
        float mn1 = fmaxf(m1, tm1);
        float cr0 = __expf(m0 - mn0);
        float cr1 = __expf(m1 - mn1);
        m0 = mn0; m1 = mn1;
        #pragma unroll
        for (int ni = 0; ni < 8; ni++) {
            oacc[ni][0] *= cr0; oacc[ni][1] *= cr0;
            oacc[ni][2] *= cr1; oacc[ni][3] *= cr1;
        }
        l0 *= cr0; l1 *= cr1;

        // p = exp(s - m), store to sKP (as P), accumulate row sums
        float rs0 = 0.f, rs1 = 0.f;
        float* prow0 = sKP + (w * 16 + g) * AT_STRIDE + 2 * t;
        float* prow1 = prow0 + 8 * AT_STRIDE;
        #pragma unroll
        for (int ni = 0; ni < 8; ni++) {
            float p0 = __expf(sc[ni][0] - mn0);
            float p1 = __expf(sc[ni][1] - mn0);
            float p2 = __expf(sc[ni][2] - mn1);
            float p3 = __expf(sc[ni][3] - mn1);
            rs0 += p0 + p1;
            rs1 += p2 + p3;
            float2 w0; w0.x = to_tf32(p0); w0.y = to_tf32(p1);
            float2 w1; w1.x = to_tf32(p2); w1.y = to_tf32(p3);
            *(float2*)(prow0 + ni * 8) = w0;
            *(float2*)(prow1 + ni * 8) = w1;
        }
        rs0 += __shfl_xor_sync(0xffffffffu, rs0, 1);
        rs0 += __shfl_xor_sync(0xffffffffu, rs0, 2);
        rs1 += __shfl_xor_sync(0xffffffffu, rs1, 1);
        rs1 += __shfl_xor_sync(0xffffffffu, rs1, 2);
        l0 += rs0; l1 += rs1;

        __syncwarp();   // P visible to own warp's fragment loads

        // O += P @ V  (16 x 64 per warp, contract over 64 keys)
        #pragma unroll
        for (int ks = 0; ks < 8; ks++) {
            const int kb = ks * 8;
            uint32_t af[4];
            const float* pbase = sKP + (w * 16 + g) * AT_STRIDE + kb + t;
            af[0] = __float_as_uint(pbase[0]);
            af[1] = __float_as_uint(pbase[8 * AT_STRIDE]);
            af[2] = __float_as_uint(pbase[4]);
            af[3] = __float_as_uint(pbase[8 * AT_STRIDE + 4]);
            #pragma unroll
            for (int ni = 0; ni < 8; ni++) {
                uint32_t bf[2];
                const float* vbase = sV + (kb + t) * AT_STRIDE + ni * 8 + g;
                bf[0] = __float_as_uint(vbase[0]);
                bf[1] = __float_as_uint(vbase[4 * AT_STRIDE]);
                mma8(oacc[ni], af, bf);
            }
        }
        __syncthreads();   // before next tile overwrites K/V
    }

    float il0 = 1.f / l0;
    float il1 = 1.f / l1;
    int row0 = q0 + w * 16 + g;
    float* o0 = o + (size_t)(b * SEQ + row0) * D_MODEL + h * DK + 2 * t;
    float* o1 = o0 + 8 * (size_t)D_MODEL;
    #pragma unroll
    for (int ni = 0; ni < 8; ni++) {
        float2 a0; a0.x = oacc[ni][0] * il0; a0.y = oacc[ni][1] * il0;
        float2 a1; a1.x = oacc[ni][2] * il1; a1.y = oacc[ni][3] * il1;
        *(float2*)(o0 + ni * 8) = a0;
        *(float2*)(o1 + ni * 8) = a1;
    }
}

// ---------------------------------------------------------------------------
extern "C" void kernel_launch(void* const* d_in, const int* in_sizes, int n_in,
                              void* d_out, int out_size) {
    const float* x  = (const float*)d_in[0];
    const float* Wq = (const float*)d_in[1];
    const float* bq = (const float*)d_in[2];
    const float* Wk = (const float*)d_in[3];
    const float* bk = (const float*)d_in[4];
    const float* Wv = (const float*)d_in[5];
    const float* bv = (const float*)d_in[6];
    const float* Wo = (const float*)d_in[7];
    const float* bo = (const float*)d_in[8];
    float* out = (float*)d_out;

    float *q, *k, *v, *att;
    cudaGetSymbolAddress((void**)&q,   g_q);
    cudaGetSymbolAddress((void**)&k,   g_k);
    cudaGetSymbolAddress((void**)&v,   g_v);
    cudaGetSymbolAddress((void**)&att, g_att);

    // Projections (tf32 tensor cores, prefetch-pipelined)
    gemm_tf32mma<<<dim3(D_MODEL/128, ROWS/128), 256>>>(x, Wq, bq, q, ROWS, D_MODEL, D_MODEL);
    gemm_tf32mma_kv<<<dim3((NKV*DK)/128, ROWS/128, 2), 256>>>(
        x, Wk, bk, k, Wv, bv, v, ROWS, NKV*DK, D_MODEL);

    // RoPE on q and k
    {
        int totq = ROWS * NH * (DK/2);
        rope_kernel<<<(totq + 255)/256, 256>>>(q, NH, totq);
        int totk = ROWS * NKV * (DK/2);
        rope_kernel<<<(totk + 255)/256, 256>>>(k, NKV, totk);
    }

    // Attention (tf32 mma flash)
    attn_mma<<<dim3(SEQ/64, BATCH*NH), 128>>>(q, k, v, att);

    // Output projection
    gemm_tf32mma<<<dim3(D_MODEL/128, ROWS/128), 256>>>(att, Wo, bo, out, ROWS, D_MODEL, D_MODEL);
}

// round 9
// speedup vs baseline: 9.9219x; 1.5728x over previous
#include <cuda_runtime.h>
#include <cuda_fp16.h>
#include <cstdint>
#include <math.h>

#define D_MODEL 2048
#define NH 32
#define NKV 8
#define DK 64
#define BATCH 2
#define SEQ 1024
#define ROWS (BATCH*SEQ)   // 2048

// fp16 scratch (static device memory)
__device__ __half g_q[ROWS * D_MODEL];          // pre-scaled by 0.125
__device__ __half g_k[ROWS * NKV * DK];
__device__ __half g_v[ROWS * NKV * DK];
__device__ __half g_att[ROWS * D_MODEL];

// ---------------------------------------------------------------------------
// PTX helpers
// ---------------------------------------------------------------------------
__device__ __forceinline__ uint32_t smem_u32(const void* p) {
    uint32_t a;
    asm("{ .reg .u64 t; cvta.to.shared.u64 t, %1; cvt.u32.u64 %0, t; }"
        : "=r"(a) : "l"(p));
    return a;
}
__device__ __forceinline__ void mma16(float* c, const uint32_t* a, const uint32_t* b) {
    asm volatile(
        "mma.sync.aligned.m16n8k16.row.col.f32.f16.f16.f32 "
        "{%0,%1,%2,%3}, {%4,%5,%6,%7}, {%8,%9}, {%0,%1,%2,%3};"
        : "+f"(c[0]), "+f"(c[1]), "+f"(c[2]), "+f"(c[3])
        : "r"(a[0]), "r"(a[1]), "r"(a[2]), "r"(a[3]), "r"(b[0]), "r"(b[1]));
}
__device__ __forceinline__ void ldsm4(uint32_t* r, uint32_t addr) {
    asm volatile("ldmatrix.sync.aligned.m8n8.x4.shared.b16 {%0,%1,%2,%3}, [%4];"
                 : "=r"(r[0]), "=r"(r[1]), "=r"(r[2]), "=r"(r[3]) : "r"(addr));
}
__device__ __forceinline__ void ldsm2(uint32_t* r, uint32_t addr) {
    asm volatile("ldmatrix.sync.aligned.m8n8.x2.shared.b16 {%0,%1}, [%2];"
                 : "=r"(r[0]), "=r"(r[1]) : "r"(addr));
}
__device__ __forceinline__ void ldsm2t(uint32_t* r, uint32_t addr) {
    asm volatile("ldmatrix.sync.aligned.m8n8.x2.trans.shared.b16 {%0,%1}, [%2];"
                 : "=r"(r[0]), "=r"(r[1]) : "r"(addr));
}
__device__ __forceinline__ uint32_t h2pack(float x, float y) {
    __half2 h = __floats2half2_rn(x, y);
    return *(uint32_t*)&h;
}

#define LOG2_THETA_OVER_HALF 0.415241011860922f   // log2(10000)/32

// ---------------------------------------------------------------------------
// fp16 tensor-core GEMM: C = A @ W + bias, optional fused RoPE + scale.
// CTA 128x128, BK=32, 256 threads = 8 warps (2x4), warp tile 64x32.
// sA: [128][40] halves (pad 8), sB: [32][136] halves (pad 8).
// ---------------------------------------------------------------------------
#define GA_STRB 80    // sA row bytes (40 halves)
#define GB_STRB 272   // sB row bytes (136 halves)

struct GSmem { __half sA[128 * 40]; __half sB[32 * 136]; };

template<bool AHALF, bool OUTHALF>
__device__ __forceinline__ void gemm_body(
        const void* __restrict__ Ap, const float* __restrict__ W,
        const float* __restrict__ bias, void* __restrict__ Cp,
        int N, int K, int do_rope, float oscale,
        GSmem& sm, int brow, int bcol) {
    const int tid  = threadIdx.x;
    const int lane = tid & 31;
    const int wid  = tid >> 5;
    const int wm   = wid >> 2;
    const int wn   = wid & 3;
    const int g    = lane >> 2;
    const int t    = lane & 3;

    const uint32_t saA = smem_u32(sm.sA);
    const uint32_t saB = smem_u32(sm.sB);

    float acc[4][4][4] = {};

    // B (weights, fp32) load mapping
    const int bkr = tid >> 5;          // 0..7
    const int bn4 = tid & 31;
    // A fp32 mapping
    const int arow = tid >> 3;         // 0..31
    const int ac4  = tid & 7;
    // A fp16 mapping
    const int hrow = tid >> 2;         // 0..63
    const int hu   = tid & 3;

    const int nchunks = K >> 5;

    float4 pa[4], pb[4];
    uint4 ph[2];
    if (AHALF) {
        const __half* A16 = (const __half*)Ap;
        #pragma unroll
        for (int it = 0; it < 2; it++)
            ph[it] = *(const uint4*)(A16 + (size_t)(brow + hrow + it * 64) * K + hu * 8);
    } else {
        const float* A = (const float*)Ap;
        #pragma unroll
        for (int it = 0; it < 4; it++)
            pa[it] = *(const float4*)(A + (size_t)(brow + arow + it * 32) * K + ac4 * 4);
    }
    #pragma unroll
    for (int it = 0; it < 4; it++)
        pb[it] = *(const float4*)(W + (size_t)(bkr + it * 8) * N + bcol + bn4 * 4);

    for (int c = 0; c < nchunks; c++) {
        // store current chunk to smem (fp16)
        if (AHALF) {
            #pragma unroll
            for (int it = 0; it < 2; it++)
                *(uint4*)((char*)sm.sA + (hrow + it * 64) * GA_STRB + hu * 16) = ph[it];
        } else {
            #pragma unroll
            for (int it = 0; it < 4; it++) {
                uint2 u;
                u.x = h2pack(pa[it].x, pa[it].y);
                u.y = h2pack(pa[it].z, pa[it].w);
                *(uint2*)((char*)sm.sA + (arow + it * 32) * GA_STRB + ac4 * 8) = u;
            }
        }
        #pragma unroll
        for (int it = 0; it < 4; it++) {
            uint2 u;
            u.x = h2pack(pb[it].x, pb[it].y);
            u.y = h2pack(pb[it].z, pb[it].w);
            *(uint2*)((char*)sm.sB + (bkr + it * 8) * GB_STRB + bn4 * 8) = u;
        }
        __syncthreads();

        // prefetch next chunk
        if (c + 1 < nchunks) {
            const int k0 = (c + 1) << 5;
            if (AHALF) {
                const __half* A16 = (const __half*)Ap;
                #pragma unroll
                for (int it = 0; it < 2; it++)
                    ph[it] = *(const uint4*)(A16 + (size_t)(brow + hrow + it * 64) * K + k0 + hu * 8);
            } else {
                const float* A = (const float*)Ap;
                #pragma unroll
                for (int it = 0; it < 4; it++)
                    pa[it] = *(const float4*)(A + (size_t)(brow + arow + it * 32) * K + k0 + ac4 * 4);
            }
            #pragma unroll
            for (int it = 0; it < 4; it++)
                pb[it] = *(const float4*)(W + (size_t)(k0 + bkr + it * 8) * N + bcol + bn4 * 4);
        }

        #pragma unroll
        for (int ks = 0; ks < 2; ks++) {
            const int kb = ks * 16;
            uint32_t af[4][4], bf[4][2];
            #pragma unroll
            for (int mi = 0; mi < 4; mi++)
                ldsm4(af[mi], saA + (wm * 64 + mi * 16 + (lane & 15)) * GA_STRB
                               + (kb + 8 * (lane >> 4)) * 2);
            #pragma unroll
            for (int ni = 0; ni < 4; ni++)
                ldsm2t(bf[ni], saB + (kb + (lane & 15)) * GB_STRB
                                + (wn * 32 + ni * 8) * 2);
            #pragma unroll
            for (int mi = 0; mi < 4; mi++)
                #pragma unroll
                for (int ni = 0; ni < 4; ni++)
                    mma16(acc[mi][ni], af[mi], bf[ni]);
        }
        __syncthreads();
    }

    // epilogue: bias (+rope) (+scale), write fp16 or fp32
    #pragma unroll
    for (int mi = 0; mi < 4; mi++) {
        const int r0 = brow + wm * 64 + mi * 16 + g;
        const int pos0 = r0 & (SEQ - 1);
        const int pos1 = (r0 + 8) & (SEQ - 1);
        #pragma unroll
        for (int ni = 0; ni < 4; ni++) {
            const int c0 = bcol + wn * 32 + ni * 8 + 2 * t;
            float2 bv = *(const float2*)(bias + c0);
            float x0 = acc[mi][ni][0] + bv.x;
            float y0 = acc[mi][ni][1] + bv.y;
            float x1 = acc[mi][ni][2] + bv.x;
            float y1 = acc[mi][ni][3] + bv.y;
            if (do_rope) {
                const int p = (c0 >> 1) & 31;
                const float invf = exp2f(-(float)p * LOG2_THETA_OVER_HALF);
                float sn, cs;
                sincosf((float)pos0 * invf, &sn, &cs);
                float nx0 = x0 * cs - y0 * sn;
                float ny0 = x0 * sn + y0 * cs;
                sincosf((float)pos1 * invf, &sn, &cs);
                float nx1 = x1 * cs - y1 * sn;
                float ny1 = x1 * sn + y1 * cs;
                x0 = nx0; y0 = ny0; x1 = nx1; y1 = ny1;
            }
            x0 *= oscale; y0 *= oscale; x1 *= oscale; y1 *= oscale;
            if (OUTHALF) {
                __half* C16 = (__half*)Cp;
                *(uint32_t*)(C16 + (size_t)r0 * N + c0)       = h2pack(x0, y0);
                *(uint32_t*)(C16 + (size_t)(r0 + 8) * N + c0) = h2pack(x1, y1);
            } else {
                float* C = (float*)Cp;
                float2 o0; o0.x = x0; o0.y = y0;
                float2 o1; o1.x = x1; o1.y = y1;
                *(float2*)(C + (size_t)r0 * N + c0)       = o0;
                *(float2*)(C + (size_t)(r0 + 8) * N + c0) = o1;
            }
        }
    }
}

__global__ __launch_bounds__(256) void gemm_proj(
        const float* __restrict__ A, const float* __restrict__ W,
        const float* __restrict__ bias, __half* __restrict__ C,
        int N, int K, int do_rope, float oscale) {
    __shared__ GSmem sm;
    gemm_body<false, true>(A, W, bias, C, N, K, do_rope, oscale,
                           sm, blockIdx.y * 128, blockIdx.x * 128);
}

__global__ __launch_bounds__(256) void gemm_kv(
        const float* __restrict__ A,
        const float* __restrict__ Wk, const float* __restrict__ bk, __half* __restrict__ Ck,
        const float* __restrict__ Wv, const float* __restrict__ bv, __half* __restrict__ Cv,
        int N, int K) {
    __shared__ GSmem sm;
    const bool isK = (blockIdx.z == 0);
    gemm_body<false, true>(A, isK ? Wk : Wv, isK ? bk : bv, isK ? Ck : Cv,
                           N, K, isK ? 1 : 0, 1.0f,
                           sm, blockIdx.y * 128, blockIdx.x * 128);
}

__global__ __launch_bounds__(256) void gemm_out(
        const __half* __restrict__ A, const float* __restrict__ W,
        const float* __restrict__ bias, float* __restrict__ C,
        int N, int K) {
    __shared__ GSmem sm;
    gemm_body<true, false>(A, W, bias, C, N, K, 0, 1.0f,
                           sm, blockIdx.y * 128, blockIdx.x * 128);
}

// ---------------------------------------------------------------------------
// fp16 mma flash attention. 128-query tile, 256 threads (8 warps x 16 rows).
// Q frags register-resident; sQ buffer reused for P. fp32 softmax.
// ---------------------------------------------------------------------------
#define AT_STRB 144   // 72 halves per row

__global__ __launch_bounds__(256) void attn_f16(
        const __half* __restrict__ q, const __half* __restrict__ k,
        const __half* __restrict__ v, __half* __restrict__ o) {
    __shared__ __half sQP[128 * 72];
    __shared__ __half sK[64 * 72];
    __shared__ __half sV[64 * 72];

    const int tid  = threadIdx.x;
    const int lane = tid & 31;
    const int w    = tid >> 5;       // 0..7
    const int g    = lane >> 2;
    const int t    = lane & 3;

    const uint32_t saQP = smem_u32(sQP);
    const uint32_t saK  = smem_u32(sK);
    const uint32_t saV  = smem_u32(sV);

    const int bh  = blockIdx.y;
    const int b   = bh >> 5;
    const int h   = bh & 31;
    const int kvh = h >> 2;
    const int q0  = (int)(gridDim.x - 1 - blockIdx.x) << 7;  // long CTAs first

    // load Q tile (128 x 64 halves), already scaled by 0.125
    #pragma unroll
    for (int it = 0; it < 4; it++) {
        int idx = tid + it * 256;
        int r = idx >> 3, u = idx & 7;
        *(uint4*)((char*)sQP + r * AT_STRB + u * 16) =
            *(const uint4*)(q + (size_t)(b * SEQ + q0 + r) * D_MODEL + h * DK + u * 8);
    }
    __syncthreads();

    // Q fragments (16 rows per warp, 4 k16 steps)
    uint32_t qf[4][4];
    #pragma unroll
    for (int ks = 0; ks < 4; ks++)
        ldsm4(qf[ks], saQP + (w * 16 + (lane & 15)) * AT_STRB
                       + (ks * 16 + 8 * (lane >> 4)) * 2);
    __syncthreads();   // sQP now reusable as P

    float oacc[8][4] = {};
    float m0 = -1e30f, m1 = -1e30f, l0 = 0.f, l1 = 0.f;

    for (int kt = 0; kt <= q0 + 64; kt += 64) {
        // load K/V tiles (64 keys x 64 halves each)
        #pragma unroll
        for (int it = 0; it < 2; it++) {
            int idx = tid + it * 256;
            int r = idx >> 3, u = idx & 7;
            size_t src = ((size_t)(b * SEQ + kt + r) * NKV + kvh) * DK + u * 8;
            *(uint4*)((char*)sK + r * AT_STRB + u * 16) = *(const uint4*)(k + src);
            *(uint4*)((char*)sV + r * AT_STRB + u * 16) = *(const uint4*)(v + src);
        }
        __syncthreads();

        // S = Q @ K^T (16 x 64 per warp)
        float sc[8][4] = {};
        #pragma unroll
        for (int ks = 0; ks < 4; ks++) {
            #pragma unroll
            for (int nk = 0; nk < 8; nk++) {
                uint32_t bf[2];
                ldsm2(bf, saK + (nk * 8 + (lane & 7)) * AT_STRB
                           + (ks * 16 + 8 * ((lane >> 3) & 1)) * 2);
                mma16(sc[nk], qf[ks], bf);
            }
        }

        // causal mask (only needed on the last two tiles)
        if (kt >= q0) {
            const int lr0 = q0 + w * 16 + g;
            const int lr1 = lr0 + 8;
            #pragma unroll
            for (int nk = 0; nk < 8; nk++) {
                const int lc = kt + nk * 8 + 2 * t;
                if (lc     > lr0) sc[nk][0] = -1e30f;
                if (lc + 1 > lr0) sc[nk][1] = -1e30f;
                if (lc     > lr1) sc[nk][2] = -1e30f;
                if (lc + 1 > lr1) sc[nk][3] = -1e30f;
            }
        }

        // row max across regs + 4 t-lanes
        float tm0 = -1e30f, tm1 = -1e30f;
        #pragma unroll
        for (int nk = 0; nk < 8; nk++) {
            tm0 = fmaxf(tm0, fmaxf(sc[nk][0], sc[nk][1]));
            tm1 = fmaxf(tm1, fmaxf(sc[nk][2], sc[nk][3]));
        }
        tm0 = fmaxf(tm0, __shfl_xor_sync(0xffffffffu, tm0, 1));
        tm0 = fmaxf(tm0, __shfl_xor_sync(0xffffffffu, tm0, 2));
        tm1 = fmaxf(tm1, __shfl_xor_sync(0xffffffffu, tm1, 1));
        tm1 = fmaxf(tm1, __shfl_xor_sync(0xffffffffu, tm1, 2));

        const float mn0 = fmaxf(m0, tm0);
        const float mn1 = fmaxf(m1, tm1);
        const float cr0 = __expf(m0 - mn0);
        const float cr1 = __expf(m1 - mn1);
        m0 = mn0; m1 = mn1;
        #pragma unroll
        for (int nd = 0; nd < 8; nd++) {
            oacc[nd][0] *= cr0; oacc[nd][1] *= cr0;
            oacc[nd][2] *= cr1; oacc[nd][3] *= cr1;
        }
        l0 *= cr0; l1 *= cr1;

        // P = exp(S - m) -> fp16 into sQP (own warp rows only)
        float rs0 = 0.f, rs1 = 0.f;
        {
            char* pr0 = (char*)sQP + (w * 16 + g) * AT_STRB + 2 * t * 2;
            char* pr1 = pr0 + 8 * AT_STRB;
            #pragma unroll
            for (int nk = 0; nk < 8; nk++) {
                float p0 = __expf(sc[nk][0] - mn0);
                float p1 = __expf(sc[nk][1] - mn0);
                float p2 = __expf(sc[nk][2] - mn1);
                float p3 = __expf(sc[nk][3] - mn1);
                rs0 += p0 + p1;
                rs1 += p2 + p3;
                *(uint32_t*)(pr0 + nk * 16) = h2pack(p0, p1);
                *(uint32_t*)(pr1 + nk * 16) = h2pack(p2, p3);
            }
        }
        rs0 += __shfl_xor_sync(0xffffffffu, rs0, 1);
        rs0 += __shfl_xor_sync(0xffffffffu, rs0, 2);
        rs1 += __shfl_xor_sync(0xffffffffu, rs1, 1);
        rs1 += __shfl_xor_sync(0xffffffffu, rs1, 2);
        l0 += rs0; l1 += rs1;
        __syncwarp();

        // O += P @ V (contract over 64 keys)
        #pragma unroll
        for (int ks = 0; ks < 4; ks++) {
            const int kb = ks * 16;
            uint32_t pf[4];
            ldsm4(pf, saQP + (w * 16 + (lane & 15)) * AT_STRB
                       + (kb + 8 * (lane >> 4)) * 2);
            #pragma unroll
            for (int nd = 0; nd < 8; nd++) {
                uint32_t bf[2];
                ldsm2t(bf, saV + (kb + (lane & 15)) * AT_STRB + nd * 16);
                mma16(oacc[nd], pf, bf);
            }
        }
        __syncthreads();   // before next tile overwrites sK/sV
    }

    const float il0 = 1.f / l0;
    const float il1 = 1.f / l1;
    const int row0 = q0 + w * 16 + g;
    __half* o0 = o + (size_t)(b * SEQ + row0) * D_MODEL + h * DK + 2 * t;
    __half* o1 = o0 + 8 * (size_t)D_MODEL;
    #pragma unroll
    for (int nd = 0; nd < 8; nd++) {
        *(uint32_t*)(o0 + nd * 8) = h2pack(oacc[nd][0] * il0, oacc[nd][1] * il0);
        *(uint32_t*)(o1 + nd * 8) = h2pack(oacc[nd][2] * il1, oacc[nd][3] * il1);
    }
}

// ---------------------------------------------------------------------------
extern "C" void kernel_launch(void* const* d_in, const int* in_sizes, int n_in,
                              void* d_out, int out_size) {
    const float* x  = (const float*)d_in[0];
    const float* Wq = (const float*)d_in[1];
    const float* bq = (const float*)d_in[2];
    const float* Wk = (const float*)d_in[3];
    const float* bk = (const float*)d_in[4];
    const float* Wv = (const float*)d_in[5];
    const float* bv = (const float*)d_in[6];
    const float* Wo = (const float*)d_in[7];
    const float* bo = (const float*)d_in[8];
    float* out = (float*)d_out;

    __half *q, *k, *v, *att;
    cudaGetSymbolAddress((void**)&q,   g_q);
    cudaGetSymbolAddress((void**)&k,   g_k);
    cudaGetSymbolAddress((void**)&v,   g_v);
    cudaGetSymbolAddress((void**)&att, g_att);

    // Q projection: rope + 1/sqrt(DK) scale fused, fp16 out
    gemm_proj<<<dim3(D_MODEL/128, ROWS/128), 256>>>(x, Wq, bq, q, D_MODEL, D_MODEL, 1, 0.125f);
    // K (rope) + V fused, fp16 out
    gemm_kv<<<dim3((NKV*DK)/128, ROWS/128, 2), 256>>>(x, Wk, bk, k, Wv, bv, v, NKV*DK, D_MODEL);
    // Attention (fp16 mma flash), fp16 out
    attn_f16<<<dim3(SEQ/128, BATCH*NH), 256>>>(q, k, v, att);
    // Output projection, fp32 out
    gemm_out<<<dim3(D_MODEL/128, ROWS/128), 256>>>(att, Wo, bo, out, D_MODEL, D_MODEL);
}

// round 14
// speedup vs baseline: 12.8402x; 1.2941x over previous
#include <cuda_runtime.h>
#include <cuda_fp16.h>
#include <cstdint>
#include <math.h>

#define D_MODEL 2048
#define NH 32
#define NKV 8
#define DK 64
#define BATCH 2
#define SEQ 1024
#define ROWS (BATCH*SEQ)   // 2048
#define NKVD (NKV*DK)      // 512

// fp16 scratch (static device memory)
__device__ __half g_x16[ROWS * D_MODEL];
__device__ __half g_wq[D_MODEL * D_MODEL];
__device__ __half g_wk[D_MODEL * NKVD];
__device__ __half g_wv[D_MODEL * NKVD];
__device__ __half g_wo[D_MODEL * D_MODEL];
__device__ __half g_q[ROWS * D_MODEL];          // pre-scaled by 0.125
__device__ __half g_k[ROWS * NKVD];
__device__ __half g_v[ROWS * NKVD];
__device__ __half g_att[ROWS * D_MODEL];

// ---------------------------------------------------------------------------
// PTX helpers
// ---------------------------------------------------------------------------
__device__ __forceinline__ uint32_t smem_u32(const void* p) {
    uint32_t a;
    asm("{ .reg .u64 t; cvta.to.shared.u64 t, %1; cvt.u32.u64 %0, t; }"
        : "=r"(a) : "l"(p));
    return a;
}
__device__ __forceinline__ void mma16(float* c, const uint32_t* a, const uint32_t* b) {
    asm volatile(
        "mma.sync.aligned.m16n8k16.row.col.f32.f16.f16.f32 "
        "{%0,%1,%2,%3}, {%4,%5,%6,%7}, {%8,%9}, {%0,%1,%2,%3};"
        : "+f"(c[0]), "+f"(c[1]), "+f"(c[2]), "+f"(c[3])
        : "r"(a[0]), "r"(a[1]), "r"(a[2]), "r"(a[3]), "r"(b[0]), "r"(b[1]));
}
__device__ __forceinline__ void ldsm4(uint32_t* r, uint32_t addr) {
    asm volatile("ldmatrix.sync.aligned.m8n8.x4.shared.b16 {%0,%1,%2,%3}, [%4];"
                 : "=r"(r[0]), "=r"(r[1]), "=r"(r[2]), "=r"(r[3]) : "r"(addr));
}
__device__ __forceinline__ void ldsm2(uint32_t* r, uint32_t addr) {
    asm volatile("ldmatrix.sync.aligned.m8n8.x2.shared.b16 {%0,%1}, [%2];"
                 : "=r"(r[0]), "=r"(r[1]) : "r"(addr));
}
__device__ __forceinline__ void ldsm2t(uint32_t* r, uint32_t addr) {
    asm volatile("ldmatrix.sync.aligned.m8n8.x2.trans.shared.b16 {%0,%1}, [%2];"
                 : "=r"(r[0]), "=r"(r[1]) : "r"(addr));
}
__device__ __forceinline__ void cpa16(uint32_t s, const void* g) {
    asm volatile("cp.async.cg.shared.global [%0], [%1], 16;" :: "r"(s), "l"(g));
}
#define CP_COMMIT()  asm volatile("cp.async.commit_group;" ::: "memory")
#define CP_WAIT1()   asm volatile("cp.async.wait_group 1;" ::: "memory")
__device__ __forceinline__ uint32_t h2pack(float x, float y) {
    __half2 h = __floats2half2_rn(x, y);
    return *(uint32_t*)&h;
}

#define LOG2_THETA_OVER_HALF 0.415241011860922f   // log2(10000)/32

// ---------------------------------------------------------------------------
// fp32 -> fp16 conversion, 5 tensors in one launch (blockIdx.y selects).
// Each thread converts 8 elements (two float4 -> one uint4 of half2s).
// ---------------------------------------------------------------------------
__global__ __launch_bounds__(256) void cvt5(
        const float* s0, __half* d0, int n0,
        const float* s1, __half* d1, int n1,
        const float* s2, __half* d2, int n2,
        const float* s3, __half* d3, int n3,
        const float* s4, __half* d4, int n4) {
    const float* s; __half* d; int n;
    switch (blockIdx.y) {
        case 0: s = s0; d = d0; n = n0; break;
        case 1: s = s1; d = d1; n = n1; break;
        case 2: s = s2; d = d2; n = n2; break;
        case 3: s = s3; d = d3; n = n3; break;
        default: s = s4; d = d4; n = n4; break;
    }
    int idx = (blockIdx.x * 256 + threadIdx.x) * 8;
    if (idx >= n) return;
    float4 a = *(const float4*)(s + idx);
    float4 b = *(const float4*)(s + idx + 4);
    uint4 o;
    o.x = h2pack(a.x, a.y); o.y = h2pack(a.z, a.w);
    o.z = h2pack(b.x, b.y); o.w = h2pack(b.z, b.w);
    *(uint4*)(d + idx) = o;
}

// ---------------------------------------------------------------------------
// fp16 x fp16 tensor-core GEMM, cp.async 2-stage pipeline.
// C = A @ W + bias, optional fused RoPE + scale.
// CTA 128x128, BK=32, 256 threads = 8 warps (2x4), warp tile 64x32.
// Per stage: sA [128][40] halves, sB [32][136] halves.
// ---------------------------------------------------------------------------
#define GA_H 40
#define GB_H 136
#define SA_H (128*GA_H)          // 5120 halves
#define SB_H (32*GB_H)           // 4352 halves
#define STAGE_H (SA_H + SB_H)    // 9472 halves
#define STAGE_B (STAGE_H * 2)    // bytes

template<bool OUTHALF>
__device__ __forceinline__ void gemm_body(
        const __half* __restrict__ A, const __half* __restrict__ W,
        const float* __restrict__ bias, void* __restrict__ Cp,
        int N, int K, int do_rope, float oscale,
        __half* smem, int brow, int bcol) {
    const int tid  = threadIdx.x;
    const int lane = tid & 31;
    const int wid  = tid >> 5;
    const int wm   = wid >> 2;
    const int wn   = wid & 3;
    const int g    = lane >> 2;
    const int t    = lane & 3;

    const uint32_t sbase = smem_u32(smem);

    // cp.async mappings: A 512 x 16B segs, B 512 x 16B segs, 2 each per thread
    const int ar = tid >> 2, au = tid & 3;
    const int br = tid >> 4, bu = tid & 15;
    const __half* gA0 = A + (size_t)(brow + ar) * K + au * 8;
    const __half* gA1 = A + (size_t)(brow + ar + 64) * K + au * 8;
    const __half* gB0 = W + (size_t)br * N + bcol + bu * 8;
    const __half* gB1 = W + (size_t)(br + 16) * N + bcol + bu * 8;
    const uint32_t sA0 = sbase + (ar * GA_H + au * 8) * 2;
    const uint32_t sA1 = sbase + ((ar + 64) * GA_H + au * 8) * 2;
    const uint32_t sB0 = sbase + (SA_H + br * GB_H + bu * 8) * 2;
    const uint32_t sB1 = sbase + (SA_H + (br + 16) * GB_H + bu * 8) * 2;

    const int nch = K >> 5;

    // prologue: chunk 0 -> stage 0
    cpa16(sA0, gA0); cpa16(sA1, gA1);
    cpa16(sB0, gB0); cpa16(sB1, gB1);
    CP_COMMIT();

    float acc[4][4][4] = {};

    for (int c = 0; c < nch; c++) {
        if (c + 1 < nch) {
            const uint32_t so = ((c + 1) & 1) * STAGE_B;
            const int k0 = (c + 1) << 5;
            cpa16(sA0 + so, gA0 + k0);
            cpa16(sA1 + so, gA1 + k0);
            cpa16(sB0 + so, gB0 + (size_t)k0 * N);
            cpa16(sB1 + so, gB1 + (size_t)k0 * N);
        }
        CP_COMMIT();          // empty group at tail keeps wait semantics uniform
        CP_WAIT1();           // oldest group (chunk c) complete
        __syncthreads();

        const uint32_t sa = sbase + (c & 1) * STAGE_B;
        const uint32_t sb = sa + SA_H * 2;

        #pragma unroll
        for (int ks = 0; ks < 2; ks++) {
            const int kb = ks * 16;
            uint32_t af[4][4], bf[4][2];
            #pragma unroll
            for (int mi = 0; mi < 4; mi++)
                ldsm4(af[mi], sa + (wm * 64 + mi * 16 + (lane & 15)) * (GA_H * 2)
                               + (kb + 8 * (lane >> 4)) * 2);
            #pragma unroll
            for (int ni = 0; ni < 4; ni++)
                ldsm2t(bf[ni], sb + (kb + (lane & 15)) * (GB_H * 2)
                                + (wn * 32 + ni * 8) * 2);
            #pragma unroll
            for (int mi = 0; mi < 4; mi++)
                #pragma unroll
                for (int ni = 0; ni < 4; ni++)
                    mma16(acc[mi][ni], af[mi], bf[ni]);
        }
        __syncthreads();      // reads done before stage is overwritten next iter
    }

    // epilogue: bias (+rope) (+scale)
    #pragma unroll
    for (int mi = 0; mi < 4; mi++) {
        const int r0 = brow + wm * 64 + mi * 16 + g;
        const int pos0 = r0 & (SEQ - 1);
        const int pos1 = (r0 + 8) & (SEQ - 1);
        #pragma unroll
        for (int ni = 0; ni < 4; ni++) {
            const int c0 = bcol + wn * 32 + ni * 8 + 2 * t;
            float2 bv = *(const float2*)(bias + c0);
            float x0 = acc[mi][ni][0] + bv.x;
            float y0 = acc[mi][ni][1] + bv.y;
            float x1 = acc[mi][ni][2] + bv.x;
            float y1 = acc[mi][ni][3] + bv.y;
            if (do_rope) {
                const int p = (c0 >> 1) & 31;
                const float invf = exp2f(-(float)p * LOG2_THETA_OVER_HALF);
                float sn, cs;
                sincosf((float)pos0 * invf, &sn, &cs);
                float nx0 = x0 * cs - y0 * sn;
                float ny0 = x0 * sn + y0 * cs;
                sincosf((float)pos1 * invf, &sn, &cs);
                float nx1 = x1 * cs - y1 * sn;
                float ny1 = x1 * sn + y1 * cs;
                x0 = nx0; y0 = ny0; x1 = nx1; y1 = ny1;
            }
            x0 *= oscale; y0 *= oscale; x1 *= oscale; y1 *= oscale;
            if (OUTHALF) {
                __half* C16 = (__half*)Cp;
                *(uint32_t*)(C16 + (size_t)r0 * N + c0)       = h2pack(x0, y0);
                *(uint32_t*)(C16 + (size_t)(r0 + 8) * N + c0) = h2pack(x1, y1);
            } else {
                float* C = (float*)Cp;
                float2 o0; o0.x = x0; o0.y = y0;
                float2 o1; o1.x = x1; o1.y = y1;
                *(float2*)(C + (size_t)r0 * N + c0)       = o0;
                *(float2*)(C + (size_t)(r0 + 8) * N + c0) = o1;
            }
        }
    }
}

__global__ __launch_bounds__(256, 2) void gemm_q(
        const __half* __restrict__ A, const __half* __restrict__ W,
        const float* __restrict__ bias, __half* __restrict__ C, int N, int K) {
    __shared__ __half sm[2 * STAGE_H];
    gemm_body<true>(A, W, bias, C, N, K, 1, 0.125f,
                    sm, blockIdx.y * 128, blockIdx.x * 128);
}

__global__ __launch_bounds__(256, 2) void gemm_kv(
        const __half* __restrict__ A,
        const __half* __restrict__ Wk, const float* __restrict__ bk, __half* __restrict__ Ck,
        const __half* __restrict__ Wv, const float* __restrict__ bv, __half* __restrict__ Cv,
        int N, int K) {
    __shared__ __half sm[2 * STAGE_H];
    const bool isK = (blockIdx.z == 0);
    gemm_body<true>(A, isK ? Wk : Wv, isK ? bk : bv, isK ? Ck : Cv,
                    N, K, isK ? 1 : 0, 1.0f,
                    sm, blockIdx.y * 128, blockIdx.x * 128);
}

__global__ __launch_bounds__(256, 2) void gemm_out(
        const __half* __restrict__ A, const __half* __restrict__ W,
        const float* __restrict__ bias, float* __restrict__ C, int N, int K) {
    __shared__ __half sm[2 * STAGE_H];
    gemm_body<false>(A, W, bias, C, N, K, 0, 1.0f,
                     sm, blockIdx.y * 128, blockIdx.x * 128);
}

// ---------------------------------------------------------------------------
// fp16 mma flash attention. 128-query tile, 256 threads (8 warps x 16 rows).
// Q frags register-resident; sQ buffer reused for P. fp32 softmax.
// ---------------------------------------------------------------------------
#define AT_STRB 144   // 72 halves per row

__global__ __launch_bounds__(256) void attn_f16(
        const __half* __restrict__ q, const __half* __restrict__ k,
        const __half* __restrict__ v, __half* __restrict__ o) {
    __shared__ __half sQP[128 * 72];
    __shared__ __half sK[64 * 72];
    __shared__ __half sV[64 * 72];

    const int tid  = threadIdx.x;
    const int lane = tid & 31;
    const int w    = tid >> 5;
    const int g    = lane >> 2;
    const int t    = lane & 3;

    const uint32_t saQP = smem_u32(sQP);
    const uint32_t saK  = smem_u32(sK);
    const uint32_t saV  = smem_u32(sV);

    const int bh  = blockIdx.y;
    const int b   = bh >> 5;
    const int h   = bh & 31;
    const int kvh = h >> 2;
    const int q0  = (int)(gridDim.x - 1 - blockIdx.x) << 7;  // long CTAs first

    // load Q tile (128 x 64 halves), already scaled by 0.125
    #pragma unroll
    for (int it = 0; it < 4; it++) {
        int idx = tid + it * 256;
        int r = idx >> 3, u = idx & 7;
        *(uint4*)((char*)sQP + r * AT_STRB + u * 16) =
            *(const uint4*)(q + (size_t)(b * SEQ + q0 + r) * D_MODEL + h * DK + u * 8);
    }
    __syncthreads();

    uint32_t qf[4][4];
    #pragma unroll
    for (int ks = 0; ks < 4; ks++)
        ldsm4(qf[ks], saQP + (w * 16 + (lane & 15)) * AT_STRB
                       + (ks * 16 + 8 * (lane >> 4)) * 2);
    __syncthreads();   // sQP now reusable as P

    float oacc[8][4] = {};
    float m0 = -1e30f, m1 = -1e30f, l0 = 0.f, l1 = 0.f;

    for (int kt = 0; kt <= q0 + 64; kt += 64) {
        #pragma unroll
        for (int it = 0; it < 2; it++) {
            int idx = tid + it * 256;
            int r = idx >> 3, u = idx & 7;
            size_t src = ((size_t)(b * SEQ + kt + r) * NKV + kvh) * DK + u * 8;
            *(uint4*)((char*)sK + r * AT_STRB + u * 16) = *(const uint4*)(k + src);
            *(uint4*)((char*)sV + r * AT_STRB + u * 16) = *(const uint4*)(v + src);
        }
        __syncthreads();

        float sc[8][4] = {};
        #pragma unroll
        for (int ks = 0; ks < 4; ks++) {
            #pragma unroll
            for (int nk = 0; nk < 8; nk++) {
                uint32_t bf[2];
                ldsm2(bf, saK + (nk * 8 + (lane & 7)) * AT_STRB
                           + (ks * 16 + 8 * ((lane >> 3) & 1)) * 2);
                mma16(sc[nk], qf[ks], bf);
            }
        }

        if (kt >= q0) {
            const int lr0 = q0 + w * 16 + g;
            const int lr1 = lr0 + 8;
            #pragma unroll
            for (int nk = 0; nk < 8; nk++) {
                const int lc = kt + nk * 8 + 2 * t;
                if (lc     > lr0) sc[nk][0] = -1e30f;
                if (lc + 1 > lr0) sc[nk][1] = -1e30f;
                if (lc     > lr1) sc[nk][2] = -1e30f;
                if (lc + 1 > lr1) sc[nk][3] = -1e30f;
            }
        }

        float tm0 = -1e30f, tm1 = -1e30f;
        #pragma unroll
        for (int nk = 0; nk < 8; nk++) {
            tm0 = fmaxf(tm0, fmaxf(sc[nk][0], sc[nk][1]));
            tm1 = fmaxf(tm1, fmaxf(sc[nk][2], sc[nk][3]));
        }
        tm0 = fmaxf(tm0, __shfl_xor_sync(0xffffffffu, tm0, 1));
        tm0 = fmaxf(tm0, __shfl_xor_sync(0xffffffffu, tm0, 2));
        tm1 = fmaxf(tm1, __shfl_xor_sync(0xffffffffu, tm1, 1));
        tm1 = fmaxf(tm1, __shfl_xor_sync(0xffffffffu, tm1, 2));

        const float mn0 = fmaxf(m0, tm0);
        const float mn1 = fmaxf(m1, tm1);
        const float cr0 = __expf(m0 - mn0);
        const float cr1 = __expf(m1 - mn1);
        m0 = mn0; m1 = mn1;
        #pragma unroll
        for (int nd = 0; nd < 8; nd++) {
            oacc[nd][0] *= cr0; oacc[nd][1] *= cr0;
            oacc[nd][2] *= cr1; oacc[nd][3] *= cr1;
        }
        l0 *= cr0; l1 *= cr1;

        float rs0 = 0.f, rs1 = 0.f;
        {
            char* pr0 = (char*)sQP + (w * 16 + g) * AT_STRB + 2 * t * 2;
            char* pr1 = pr0 + 8 * AT_STRB;
            #pragma unroll
            for (int nk = 0; nk < 8; nk++) {
                float p0 = __expf(sc[nk][0] - mn0);
                float p1 = __expf(sc[nk][1] - mn0);
                float p2 = __expf(sc[nk][2] - mn1);
                float p3 = __expf(sc[nk][3] - mn1);
                rs0 += p0 + p1;
                rs1 += p2 + p3;
                *(uint32_t*)(pr0 + nk * 16) = h2pack(p0, p1);
                *(uint32_t*)(pr1 + nk * 16) = h2pack(p2, p3);
            }
        }
        rs0 += __shfl_xor_sync(0xffffffffu, rs0, 1);
        rs0 += __shfl_xor_sync(0xffffffffu, rs0, 2);
        rs1 += __shfl_xor_sync(0xffffffffu, rs1, 1);
        rs1 += __shfl_xor_sync(0xffffffffu, rs1, 2);
        l0 += rs0; l1 += rs1;
        __syncwarp();

        #pragma unroll
        for (int ks = 0; ks < 4; ks++) {
            const int kb = ks * 16;
            uint32_t pf[4];
            ldsm4(pf, saQP + (w * 16 + (lane & 15)) * AT_STRB
                       + (kb + 8 * (lane >> 4)) * 2);
            #pragma unroll
            for (int nd = 0; nd < 8; nd++) {
                uint32_t bf[2];
                ldsm2t(bf, saV + (kb + (lane & 15)) * AT_STRB + nd * 16);
                mma16(oacc[nd], pf, bf);
            }
        }
        __syncthreads();
    }

    const float il0 = 1.f / l0;
    const float il1 = 1.f / l1;
    const int row0 = q0 + w * 16 + g;
    __half* o0 = o + (size_t)(b * SEQ + row0) * D_MODEL + h * DK + 2 * t;
    __half* o1 = o0 + 8 * (size_t)D_MODEL;
    #pragma unroll
    for (int nd = 0; nd < 8; nd++) {
        *(uint32_t*)(o0 + nd * 8) = h2pack(oacc[nd][0] * il0, oacc[nd][1] * il0);
        *(uint32_t*)(o1 + nd * 8) = h2pack(oacc[nd][2] * il1, oacc[nd][3] * il1);
    }
}

// ---------------------------------------------------------------------------
extern "C" void kernel_launch(void* const* d_in, const int* in_sizes, int n_in,
                              void* d_out, int out_size) {
    const float* x  = (const float*)d_in[0];
    const float* Wq = (const float*)d_in[1];
    const float* bq = (const float*)d_in[2];
    const float* Wk = (const float*)d_in[3];
    const float* bk = (const float*)d_in[4];
    const float* Wv = (const float*)d_in[5];
    const float* bv = (const float*)d_in[6];
    const float* Wo = (const float*)d_in[7];
    const float* bo = (const float*)d_in[8];
    float* out = (float*)d_out;

    __half *x16, *wq, *wk, *wv, *wo, *q, *k, *v, *att;
    cudaGetSymbolAddress((void**)&x16, g_x16);
    cudaGetSymbolAddress((void**)&wq,  g_wq);
    cudaGetSymbolAddress((void**)&wk,  g_wk);
    cudaGetSymbolAddress((void**)&wv,  g_wv);
    cudaGetSymbolAddress((void**)&wo,  g_wo);
    cudaGetSymbolAddress((void**)&q,   g_q);
    cudaGetSymbolAddress((void**)&k,   g_k);
    cudaGetSymbolAddress((void**)&v,   g_v);
    cudaGetSymbolAddress((void**)&att, g_att);

    // fp32 -> fp16 conversion of x and all weights
    cvt5<<<dim3(2048, 5), 256>>>(
        x,  x16, ROWS * D_MODEL,
        Wq, wq,  D_MODEL * D_MODEL,
        Wk, wk,  D_MODEL * NKVD,
        Wv, wv,  D_MODEL * NKVD,
        Wo, wo,  D_MODEL * D_MODEL);

    // Q projection: rope + 1/sqrt(DK) fused
    gemm_q<<<dim3(D_MODEL/128, ROWS/128), 256>>>(x16, wq, bq, q, D_MODEL, D_MODEL);
    // K (rope) + V fused
    gemm_kv<<<dim3(NKVD/128, ROWS/128, 2), 256>>>(x16, wk, bk, k, wv, bv, v, NKVD, D_MODEL);
    // Attention
    attn_f16<<<dim3(SEQ/128, BATCH*NH), 256>>>(q, k, v, att);
    // Output projection (fp32 out)
    gemm_out<<<dim3(D_MODEL/128, ROWS/128), 256>>>(att, wo, bo, out, D_MODEL, D_MODEL);
}